// round 4
// baseline (speedup 1.0000x reference)
#include <cuda_runtime.h>
#include <cstdint>

#define EMB      128
#define NRAD     6
#define NDENSE   3
#define NT       12      // num targets
#define NTP      16      // padded targets in smem
#define MAX_ATOMS 20480
#define MAX_EDGES 660000

#define MLP_ROWS  136    // rows per MLP block (1 block/SM, one wave)
#define MLP_PAIRS 68     // row pairs per block
#define PH        69     // float2 pitch for h tile in smem (padded)

// -------- persistent device scratch (no allocations allowed) --------
__device__ float g_h[MAX_ATOMS * EMB];   // gathered atom features
__device__ int   g_row[MAX_ATOMS + 1];   // CSR row offsets
__device__ int   g_cnt[MAX_ATOMS];       // histogram counts (zero-init; re-zeroed by fill)
__device__ int   g_cursor[MAX_ATOMS];    // fill cursors
__device__ int   g_edges[MAX_EDGES];     // CSR edge ids

typedef unsigned long long u64;

// -------- packed fp32x2 helpers (full-rate fp32 on Blackwell) --------
__device__ __forceinline__ u64 ffma2(u64 a, u64 b, u64 c) {
    u64 d;
    asm("fma.rn.f32x2 %0, %1, %2, %3;" : "=l"(d) : "l"(a), "l"(b), "l"(c));
    return d;
}
__device__ __forceinline__ u64 pack2(float x, float y) {
    u64 r;
    asm("mov.b64 %0, {%1, %2};" : "=l"(r) : "f"(x), "f"(y));
    return r;
}
__device__ __forceinline__ void unpack2(u64 v, float& x, float& y) {
    asm("mov.b64 {%0, %1}, %2;" : "=f"(x), "=f"(y) : "l"(v));
}
__device__ __forceinline__ float silu_f(float x) {
    return x / (1.0f + __expf(-x));
}

// -------- inline int64/int32 detection (per block, deterministic) --------
// int32 data read as int64 merges adjacent indices -> out of [0,n_atoms)
// with overwhelming probability over 2048 words.
__device__ __forceinline__ bool detect_is64(const void* idnb, int E, int n_atoms,
                                            int* s_flag) {
    if (threadIdx.x < 32) {
        const long long* p = (const long long*)idnb;
        int n = E / 2;
        if (n > 2048) n = 2048;
        int bad = 0;
        for (int i = threadIdx.x; i < n; i += 32) {
            long long v = p[i];
            if (v < 0 || v >= (long long)n_atoms) bad = 1;
        }
        bad = __any_sync(0xffffffffu, bad) ? 1 : 0;
        if (threadIdx.x == 0) *s_flag = bad ? 0 : 1;
    }
    __syncthreads();
    return *s_flag != 0;
}

// ===================================================================
// Kernel 0: histogram of destination atoms (g_cnt pre-zeroed: static
// init on first call, re-zeroed by fill_kernel on every call).
// ===================================================================
__global__ void hist_kernel(const void* __restrict__ idnb, int E, int n_atoms) {
    __shared__ int s_flag;
    const bool is64 = detect_is64(idnb, E, n_atoms, &s_flag);
    const long long* i64 = (const long long*)idnb;
    const int* i32 = (const int*)idnb;
    for (int e = blockIdx.x * blockDim.x + threadIdx.x; e < E;
         e += gridDim.x * blockDim.x) {
        const int idx = is64 ? (int)i64[e] : i32[e];
        atomicAdd(&g_cnt[idx], 1);
    }
}

// ===================================================================
// Kernel 1: exclusive prefix sum -> row offsets + cursors.
// Register-staged: all chunk loads issued independently.
// ===================================================================
#define SCAN_CH 20   // covers n_atoms <= 20480 with 1024 threads
__global__ void scan_kernel(int n_atoms, int E) {
    __shared__ int wtot[32];
    const int t = threadIdx.x;
    const int lane = t & 31, wid = t >> 5;
    const int c0 = t * SCAN_CH;

    int v[SCAN_CH];
#pragma unroll
    for (int i = 0; i < SCAN_CH; ++i) {
        const int c = c0 + i;
        v[i] = (c < n_atoms) ? g_cnt[c] : 0;
    }
    int sum = 0;
#pragma unroll
    for (int i = 0; i < SCAN_CH; ++i) sum += v[i];

    int inc = sum;
#pragma unroll
    for (int d = 1; d < 32; d <<= 1) {
        int u = __shfl_up_sync(0xffffffffu, inc, d);
        if (lane >= d) inc += u;
    }
    if (lane == 31) wtot[wid] = inc;
    __syncthreads();
    if (wid == 0) {
        int u = wtot[lane];
#pragma unroll
        for (int d = 1; d < 32; d <<= 1) {
            int p = __shfl_up_sync(0xffffffffu, u, d);
            if (lane >= d) u += p;
        }
        wtot[lane] = u;
    }
    __syncthreads();

    int run = inc - sum + (wid > 0 ? wtot[wid - 1] : 0);
#pragma unroll
    for (int i = 0; i < SCAN_CH; ++i) {
        const int c = c0 + i;
        if (c < n_atoms) {
            g_row[c] = run;
            g_cursor[c] = run;
            run += v[i];
        }
    }
    if (t == 0) g_row[n_atoms] = E;
}

// ===================================================================
// Kernel 2: fill CSR edge lists; also re-zero g_cnt for the NEXT
// graph replay (scan has already consumed it).
// ===================================================================
__global__ void fill_kernel(const void* __restrict__ idnb, int E, int n_atoms) {
    __shared__ int s_flag;
    const bool is64 = detect_is64(idnb, E, n_atoms, &s_flag);
    const long long* i64 = (const long long*)idnb;
    const int* i32 = (const int*)idnb;
    const int g0 = blockIdx.x * blockDim.x + threadIdx.x;
    const int gs = gridDim.x * blockDim.x;
    for (int i = g0; i < n_atoms; i += gs) g_cnt[i] = 0;
    for (int e = g0; e < E; e += gs) {
        const int idx = is64 ? (int)i64[e] : i32[e];
        const int pos = atomicAdd(&g_cursor[idx], 1);
        g_edges[pos] = e;
    }
}

// ===================================================================
// Kernel 3 (PROFILED SLOT): gather + gate. One warp per atom.
// ===================================================================
__global__ __launch_bounds__(256)
void gather_kernel(const float* __restrict__ x,
                   const float* __restrict__ rbf,
                   const float* __restrict__ Wrbf,
                   int n_atoms) {
    const int lane = threadIdx.x & 31;
    const int gw = (blockIdx.x * blockDim.x + threadIdx.x) >> 5;
    const int nw = (gridDim.x * blockDim.x) >> 5;
    const unsigned FULL = 0xffffffffu;

    float4 w[NRAD];
    const float4* w4 = (const float4*)Wrbf;
#pragma unroll
    for (int r = 0; r < NRAD; ++r) w[r] = w4[r * 32 + lane];

    const float4* x4 = (const float4*)x;

    for (int a = gw; a < n_atoms; a += nw) {
        const int s  = __ldg(&g_row[a]);
        const int e1 = __ldg(&g_row[a + 1]);
        float a0 = 0.f, a1 = 0.f, a2 = 0.f, a3 = 0.f;

        for (int base = s; base < e1; base += 32) {
            const int n = min(32, e1 - base);            // >= 1
            const int eid = __ldg(&g_edges[base + min(lane, n - 1)]);

            const float* rp = rbf + (size_t)eid * NRAD;
            const float rb0 = __ldcs(rp + 0), rb1 = __ldcs(rp + 1);
            const float rb2 = __ldcs(rp + 2), rb3 = __ldcs(rp + 3);
            const float rb4 = __ldcs(rp + 4), rb5 = __ldcs(rp + 5);

            for (int j = 0; j < n; j += 8) {
                int    e[8];
                float4 xv[8];
#pragma unroll
                for (int u = 0; u < 8; ++u) {
                    const int jj = min(j + u, n - 1);
                    e[u] = __shfl_sync(FULL, eid, jj);
                }
#pragma unroll
                for (int u = 0; u < 8; ++u)
                    xv[u] = __ldcs(x4 + (size_t)e[u] * 32 + lane);
#pragma unroll
                for (int u = 0; u < 8; ++u) {
                    const int jj = min(j + u, n - 1);
                    const float m = (j + u < n) ? 1.f : 0.f;
                    const float r0 = __shfl_sync(FULL, rb0, jj);
                    const float r1 = __shfl_sync(FULL, rb1, jj);
                    const float r2 = __shfl_sync(FULL, rb2, jj);
                    const float r3 = __shfl_sync(FULL, rb3, jj);
                    const float r4 = __shfl_sync(FULL, rb4, jj);
                    const float r5 = __shfl_sync(FULL, rb5, jj);

                    float g0 = fmaf(r0, w[0].x, fmaf(r1, w[1].x, fmaf(r2, w[2].x,
                               fmaf(r3, w[3].x, fmaf(r4, w[4].x, r5 * w[5].x)))));
                    float g1 = fmaf(r0, w[0].y, fmaf(r1, w[1].y, fmaf(r2, w[2].y,
                               fmaf(r3, w[3].y, fmaf(r4, w[4].y, r5 * w[5].y)))));
                    float g2 = fmaf(r0, w[0].z, fmaf(r1, w[1].z, fmaf(r2, w[2].z,
                               fmaf(r3, w[3].z, fmaf(r4, w[4].z, r5 * w[5].z)))));
                    float g3 = fmaf(r0, w[0].w, fmaf(r1, w[1].w, fmaf(r2, w[2].w,
                               fmaf(r3, w[3].w, fmaf(r4, w[4].w, r5 * w[5].w)))));

                    a0 = fmaf(m * g0, xv[u].x, a0);
                    a1 = fmaf(m * g1, xv[u].y, a1);
                    a2 = fmaf(m * g2, xv[u].z, a2);
                    a3 = fmaf(m * g3, xv[u].w, a3);
                }
            }
        }
        ((float4*)(g_h + (size_t)a * EMB))[lane] = make_float4(a0, a1, a2, a3);
    }
}

// ===================================================================
// Kernel 4: fused MLP head. 1024 threads, 136 rows/block, 1 block/SM,
// grid = ceil(n_atoms/136) = 148 -> exactly one wave, 32 warps/SM.
// Each thread owns 2 output columns; h pairs via broadcast LDS.64.
// ===================================================================
#define HS_BYTES   (EMB * PH * 8)          // 70656
#define WS_OFF     HS_BYTES
#define WS_BYTES   (EMB * EMB * 4)         // 65536
#define WFS_OFF    (WS_OFF + WS_BYTES)     // 136192
#define WFS_BYTES  (EMB * NTP * 4)         // 8192
#define BS_OFF     (WFS_OFF + WFS_BYTES)   // 144384
#define BS_BYTES   (EMB * 4)               // 512
#define SMEM_TOTAL (BS_OFF + BS_BYTES)     // 144896

__global__ __launch_bounds__(1024, 1)
void mlp_kernel(const float* __restrict__ dW, const float* __restrict__ dB,
                const float* __restrict__ Wf, float* __restrict__ out,
                int n_atoms) {
    extern __shared__ char smem[];
    u64*   hsu = (u64*)smem;                       // [col][pair], pitch PH
    float* hsf = (float*)smem;                     // float view, pitch 2*PH
    float* Ws  = (float*)(smem + WS_OFF);          // layer weight [k][j]
    float* Wfs = (float*)(smem + WFS_OFF);         // final weight [k][c] pad 16
    float* bss = (float*)(smem + BS_OFF);          // bias

    const int t = threadIdx.x;
    const int rowbase = blockIdx.x * MLP_ROWS;

    // ---- load h tile (coalesced global, transpose into [col][row]) ----
    for (int idx = t; idx < MLP_ROWS * EMB; idx += 1024) {
        const int r = idx >> 7, c = idx & 127;
        const int gr = rowbase + r;
        const float v = (gr < n_atoms) ? g_h[(size_t)gr * EMB + c] : 0.f;
        hsf[c * (2 * PH) + r] = v;
    }
    if (t < EMB) {
#pragma unroll
        for (int c = 0; c < NT; ++c) Wfs[t * NTP + c] = Wf[t * NT + c];
    }

    const int j0 = (t & 63) * 2;   // 2 output columns per thread
    const int pg = t >> 6;         // pair group 0..15

    // ---- dense layers ----
    for (int li = 0; li < NDENSE; ++li) {
        const float* W = dW + (size_t)li * EMB * EMB;
        for (int idx = t; idx < EMB * EMB; idx += 1024) Ws[idx] = W[idx];
        if (t < EMB) bss[t] = dB[li * EMB + t];
        __syncthreads();

        u64 acc[5][2];
#pragma unroll
        for (int p = 0; p < 5; ++p) { acc[p][0] = 0ull; acc[p][1] = 0ull; }

#pragma unroll 4
        for (int k = 0; k < EMB; ++k) {
            const float2 wv = *(const float2*)&Ws[k * EMB + j0];
            const u64 w0 = pack2(wv.x, wv.x);
            const u64 w1 = pack2(wv.y, wv.y);
            const u64* hrow = hsu + k * PH;
#pragma unroll
            for (int p = 0; p < 4; ++p) {
                const u64 hv = hrow[pg + p * 16];
                acc[p][0] = ffma2(hv, w0, acc[p][0]);
                acc[p][1] = ffma2(hv, w1, acc[p][1]);
            }
            if (pg < 4) {   // tail pairs 64..67 (uniform per warp)
                const u64 hv = hrow[64 + pg];
                acc[4][0] = ffma2(hv, w0, acc[4][0]);
                acc[4][1] = ffma2(hv, w1, acc[4][1]);
            }
        }

        const float b0 = bss[j0], b1 = bss[j0 + 1];
        __syncthreads();   // all reads of hs done -> safe to overwrite

#pragma unroll
        for (int p = 0; p < 5; ++p) {
            if (p == 4 && pg >= 4) break;
            const int pr = (p < 4) ? (pg + p * 16) : (64 + pg);
            float lo, hi;
            unpack2(acc[p][0], lo, hi);
            lo = silu_f(lo + b0); hi = silu_f(hi + b0);
            hsu[j0 * PH + pr] = pack2(lo, hi);
            unpack2(acc[p][1], lo, hi);
            lo = silu_f(lo + b1); hi = silu_f(hi + b1);
            hsu[(j0 + 1) * PH + pr] = pack2(lo, hi);
        }
        __syncthreads();
    }

    // ---- final projection: [136,128] @ [128,12] -> out ----
    const int c = t & 15;
    const int grp = t >> 4;      // 0..63
    if (c < NT) {
#pragma unroll
        for (int i = 0; i < 2; ++i) {
            const int pr = grp + 64 * i;
            if (pr < MLP_PAIRS) {
                u64 acc = 0ull;
#pragma unroll 4
                for (int k = 0; k < EMB; ++k) {
                    const float wfv = Wfs[k * NTP + c];
                    acc = ffma2(hsu[k * PH + pr], pack2(wfv, wfv), acc);
                }
                float lo, hi;
                unpack2(acc, lo, hi);
                const int r0 = rowbase + 2 * pr;
                if (r0 < n_atoms)     out[(size_t)r0 * NT + c]       = lo;
                if (r0 + 1 < n_atoms) out[(size_t)(r0 + 1) * NT + c] = hi;
            }
        }
    }
}

// ===================================================================
extern "C" void kernel_launch(void* const* d_in, const int* in_sizes, int n_in,
                              void* d_out, int out_size) {
    const float* x    = (const float*)d_in[0];
    const float* rbf  = (const float*)d_in[1];
    const void*  idnb =               d_in[2];
    // d_in[3] = n_atoms scalar (derive from out_size instead)
    const float* Wrbf = (const float*)d_in[4];
    const float* dW   = (const float*)d_in[5];
    const float* dB   = (const float*)d_in[6];
    const float* Wf   = (const float*)d_in[7];
    float* out = (float*)d_out;

    const int E = in_sizes[0] / EMB;
    const int n_atoms = out_size / NT;

    hist_kernel<<<592, 256>>>(idnb, E, n_atoms);            // launch 0
    scan_kernel<<<1, 1024>>>(n_atoms, E);                   // launch 1
    fill_kernel<<<592, 256>>>(idnb, E, n_atoms);            // launch 2
    gather_kernel<<<1184, 256>>>(x, rbf, Wrbf, n_atoms);    // launch 3 (profiled)

    cudaFuncSetAttribute(mlp_kernel, cudaFuncAttributeMaxDynamicSharedMemorySize,
                         SMEM_TOTAL);
    const int blocks = (n_atoms + MLP_ROWS - 1) / MLP_ROWS;
    mlp_kernel<<<blocks, 1024, SMEM_TOTAL>>>(dW, dB, Wf, out, n_atoms);
}

// round 5
// speedup vs baseline: 1.3245x; 1.3245x over previous
#include <cuda_runtime.h>
#include <cstdint>

#define EMB      128
#define NRAD     6
#define NDENSE   3
#define NT       12      // num targets
#define NTP      16      // padded targets in smem
#define MAX_ATOMS 20480
#define MAX_EDGES 660000

#define MLP_ROWS  136    // rows per MLP block (1 block/SM, one wave)
#define MLP_PAIRS 68     // row pairs per block
#define PH        69     // float2 pitch for h tile in smem (padded)

// -------- persistent device scratch (no allocations allowed) --------
__device__ __align__(16) float g_h[MAX_ATOMS * EMB];
__device__ __align__(16) int   g_row[MAX_ATOMS + 4];  // CSR offsets (padded for int4)
__device__ __align__(16) int   g_cnt[MAX_ATOMS];      // counts (zero-init; re-zeroed by fill)
__device__ __align__(16) int   g_cursor[MAX_ATOMS];
__device__ int   g_edges[MAX_EDGES];

typedef unsigned long long u64;

// -------- packed fp32x2 helpers (full-rate fp32 on Blackwell) --------
__device__ __forceinline__ u64 ffma2(u64 a, u64 b, u64 c) {
    u64 d;
    asm("fma.rn.f32x2 %0, %1, %2, %3;" : "=l"(d) : "l"(a), "l"(b), "l"(c));
    return d;
}
__device__ __forceinline__ u64 pack2(float x, float y) {
    u64 r;
    asm("mov.b64 %0, {%1, %2};" : "=l"(r) : "f"(x), "f"(y));
    return r;
}
__device__ __forceinline__ void unpack2(u64 v, float& x, float& y) {
    asm("mov.b64 {%0, %1}, %2;" : "=f"(x), "=f"(y) : "l"(v));
}
__device__ __forceinline__ float silu_f(float x) {
    return x / (1.0f + __expf(-x));
}

// -------- cp.async helpers --------
__device__ __forceinline__ void cp_async16(uint32_t saddr, const void* gptr) {
    asm volatile("cp.async.cg.shared.global [%0], [%1], 16;"
                 :: "r"(saddr), "l"(gptr) : "memory");
}
__device__ __forceinline__ void cp_commit() {
    asm volatile("cp.async.commit_group;" ::: "memory");
}
__device__ __forceinline__ void cp_wait2() {
    asm volatile("cp.async.wait_group 2;" ::: "memory");
}

// -------- inline int64/int32 detection (per block, deterministic) --------
__device__ __forceinline__ bool detect_is64(const void* idnb, int E, int n_atoms,
                                            int* s_flag) {
    if (threadIdx.x < 32) {
        const long long* p = (const long long*)idnb;
        int n = E / 2;
        if (n > 2048) n = 2048;
        int bad = 0;
        for (int i = threadIdx.x; i < n; i += 32) {
            long long v = p[i];
            if (v < 0 || v >= (long long)n_atoms) bad = 1;
        }
        bad = __any_sync(0xffffffffu, bad) ? 1 : 0;
        if (threadIdx.x == 0) *s_flag = bad ? 0 : 1;
    }
    __syncthreads();
    return *s_flag != 0;
}

// ===================================================================
// Kernel 0: histogram of destination atoms.
// ===================================================================
__global__ void hist_kernel(const void* __restrict__ idnb, int E, int n_atoms) {
    __shared__ int s_flag;
    const bool is64 = detect_is64(idnb, E, n_atoms, &s_flag);
    const long long* i64 = (const long long*)idnb;
    const int* i32 = (const int*)idnb;
    for (int e = blockIdx.x * blockDim.x + threadIdx.x; e < E;
         e += gridDim.x * blockDim.x) {
        const int idx = is64 ? (int)i64[e] : i32[e];
        atomicAdd(&g_cnt[idx], 1);
    }
}

// ===================================================================
// Kernel 1: exclusive prefix sum -> row offsets + cursors.
// Fully vectorized int4 loads/stores; entries beyond n_atoms are
// provably zero (never touched), so no bounds checks needed and
// g_row[n_atoms] = E falls out of the scan automatically.
// ===================================================================
#define SCAN_CH 20   // 1024 threads x 20 = 20480 >= n_atoms
__global__ void scan_kernel(int n_atoms, int E) {
    __shared__ int wtot[32];
    const int t = threadIdx.x;
    const int lane = t & 31, wid = t >> 5;
    const int c0 = t * SCAN_CH;           // multiple of 4 -> int4 aligned

    int4 vv[5];
    const int4* cp4 = (const int4*)(g_cnt + c0);
#pragma unroll
    for (int i = 0; i < 5; ++i) vv[i] = cp4[i];
    const int* v = (const int*)vv;

    int sum = 0;
#pragma unroll
    for (int i = 0; i < SCAN_CH; ++i) sum += v[i];

    int inc = sum;
#pragma unroll
    for (int d = 1; d < 32; d <<= 1) {
        int u = __shfl_up_sync(0xffffffffu, inc, d);
        if (lane >= d) inc += u;
    }
    if (lane == 31) wtot[wid] = inc;
    __syncthreads();
    if (wid == 0) {
        int u = wtot[lane];
#pragma unroll
        for (int d = 1; d < 32; d <<= 1) {
            int p = __shfl_up_sync(0xffffffffu, u, d);
            if (lane >= d) u += p;
        }
        wtot[lane] = u;
    }
    __syncthreads();

    int run = inc - sum + (wid > 0 ? wtot[wid - 1] : 0);
    int4 ov[5];
    int* o = (int*)ov;
#pragma unroll
    for (int i = 0; i < SCAN_CH; ++i) { o[i] = run; run += v[i]; }

    int4* r4 = (int4*)(g_row + c0);
    int4* u4 = (int4*)(g_cursor + c0);
#pragma unroll
    for (int i = 0; i < 5; ++i) { r4[i] = ov[i]; u4[i] = ov[i]; }
    // position n_atoms (if within this range) received run == E automatically.
}

// ===================================================================
// Kernel 2: fill CSR edge lists; re-zero g_cnt for next graph replay.
// ===================================================================
__global__ void fill_kernel(const void* __restrict__ idnb, int E, int n_atoms) {
    __shared__ int s_flag;
    const bool is64 = detect_is64(idnb, E, n_atoms, &s_flag);
    const long long* i64 = (const long long*)idnb;
    const int* i32 = (const int*)idnb;
    const int g0 = blockIdx.x * blockDim.x + threadIdx.x;
    const int gs = gridDim.x * blockDim.x;
    for (int i = g0; i < n_atoms; i += gs) g_cnt[i] = 0;
    for (int e = g0; e < E; e += gs) {
        const int idx = is64 ? (int)i64[e] : i32[e];
        const int pos = atomicAdd(&g_cursor[idx], 1);
        g_edges[pos] = e;
    }
}

// ===================================================================
// Kernel 3 (PROFILED SLOT): gather + gate, cp.async staged.
// One warp per atom. x rows flow global->SMEM via a 3-stage x 4-edge
// cp.async ring (6KB/warp, 48KB/block). Each lane stages & consumes
// only its own 16B slot -> no cross-lane sync. Slot WAR safe: the
// refill cp.async for slot s issues only after the FMAs that consumed
// the prior LDS of s have issued (in-order warp issue).
// ===================================================================
#define GS 3   // pipeline stages
#define GE 4   // edges per stage

__global__ __launch_bounds__(256, 4)
void gather_kernel(const float* __restrict__ x,
                   const float* __restrict__ rbf,
                   const float* __restrict__ Wrbf,
                   int n_atoms) {
    __shared__ float4 sx[8][GS * GE][32];   // 49152 B
    const int wl   = threadIdx.x >> 5;
    const int lane = threadIdx.x & 31;
    const int gw = (blockIdx.x * blockDim.x + threadIdx.x) >> 5;
    const int nw = (gridDim.x * blockDim.x) >> 5;
    const unsigned FULL = 0xffffffffu;

    const uint32_t sbase =
        (uint32_t)__cvta_generic_to_shared(&sx[wl][0][lane]);  // +512B per slot

    float4 w[NRAD];
    const float4* w4 = (const float4*)Wrbf;
#pragma unroll
    for (int r = 0; r < NRAD; ++r) w[r] = w4[r * 32 + lane];

    const float4* x4 = (const float4*)x;

    for (int a = gw; a < n_atoms; a += nw) {
        const int s  = __ldg(&g_row[a]);
        const int e1 = __ldg(&g_row[a + 1]);
        float a0 = 0.f, a1 = 0.f, a2 = 0.f, a3 = 0.f;

        for (int base = s; base < e1; base += 32) {
            const int n = min(32, e1 - base);            // >= 1, warp-uniform
            const int eid = __ldg(&g_edges[base + min(lane, n - 1)]);

            const float* rp = rbf + (size_t)eid * NRAD;
            const float rb0 = __ldcs(rp + 0), rb1 = __ldcs(rp + 1);
            const float rb2 = __ldcs(rp + 2), rb3 = __ldcs(rp + 3);
            const float rb4 = __ldcs(rp + 4), rb5 = __ldcs(rp + 5);

            const int ng = (n + 3) >> 2;

            // prologue: fill up to GS stages (empty commits keep count)
#pragma unroll
            for (int g = 0; g < GS; ++g) {
                if (g < ng) {
#pragma unroll
                    for (int u = 0; u < GE; ++u) {
                        const int jj = min(g * GE + u, n - 1);
                        const int e = __shfl_sync(FULL, eid, jj);
                        cp_async16(sbase + (uint32_t)(g * GE + u) * 512u,
                                   x4 + (size_t)e * 32 + lane);
                    }
                }
                cp_commit();
            }

            for (int g = 0; g < ng; ++g) {
                cp_wait2();                      // group g data landed
                const int slot0 = (g % GS) * GE;
#pragma unroll
                for (int u = 0; u < GE; ++u) {
                    const int je = g * GE + u;
                    const int jj = min(je, n - 1);
                    const float m = (je < n) ? 1.f : 0.f;
                    const float r0 = __shfl_sync(FULL, rb0, jj);
                    const float r1 = __shfl_sync(FULL, rb1, jj);
                    const float r2 = __shfl_sync(FULL, rb2, jj);
                    const float r3 = __shfl_sync(FULL, rb3, jj);
                    const float r4 = __shfl_sync(FULL, rb4, jj);
                    const float r5 = __shfl_sync(FULL, rb5, jj);

                    const float4 xv = sx[wl][slot0 + u][lane];

                    float g0 = fmaf(r0, w[0].x, fmaf(r1, w[1].x, fmaf(r2, w[2].x,
                               fmaf(r3, w[3].x, fmaf(r4, w[4].x, r5 * w[5].x)))));
                    float g1 = fmaf(r0, w[0].y, fmaf(r1, w[1].y, fmaf(r2, w[2].y,
                               fmaf(r3, w[3].y, fmaf(r4, w[4].y, r5 * w[5].y)))));
                    float g2 = fmaf(r0, w[0].z, fmaf(r1, w[1].z, fmaf(r2, w[2].z,
                               fmaf(r3, w[3].z, fmaf(r4, w[4].z, r5 * w[5].z)))));
                    float g3 = fmaf(r0, w[0].w, fmaf(r1, w[1].w, fmaf(r2, w[2].w,
                               fmaf(r3, w[3].w, fmaf(r4, w[4].w, r5 * w[5].w)))));

                    a0 = fmaf(m * g0, xv.x, a0);
                    a1 = fmaf(m * g1, xv.y, a1);
                    a2 = fmaf(m * g2, xv.z, a2);
                    a3 = fmaf(m * g3, xv.w, a3);
                }
                // refill this slot with group g+GS (after consume -> WAR safe)
                const int gi = g + GS;
                if (gi < ng) {
#pragma unroll
                    for (int u = 0; u < GE; ++u) {
                        const int jj = min(gi * GE + u, n - 1);
                        const int e = __shfl_sync(FULL, eid, jj);
                        cp_async16(sbase + (uint32_t)((gi % GS) * GE + u) * 512u,
                                   x4 + (size_t)e * 32 + lane);
                    }
                }
                cp_commit();
            }
        }
        ((float4*)(g_h + (size_t)a * EMB))[lane] = make_float4(a0, a1, a2, a3);
    }
}

// ===================================================================
// Kernel 4: fused MLP head (1024 thr, 136 rows/block, one wave).
// ===================================================================
#define HS_BYTES   (EMB * PH * 8)          // 70656
#define WS_OFF     HS_BYTES
#define WS_BYTES   (EMB * EMB * 4)         // 65536
#define WFS_OFF    (WS_OFF + WS_BYTES)     // 136192
#define WFS_BYTES  (EMB * NTP * 4)         // 8192
#define BS_OFF     (WFS_OFF + WFS_BYTES)   // 144384
#define BS_BYTES   (EMB * 4)               // 512
#define SMEM_TOTAL (BS_OFF + BS_BYTES)     // 144896

__global__ __launch_bounds__(1024, 1)
void mlp_kernel(const float* __restrict__ dW, const float* __restrict__ dB,
                const float* __restrict__ Wf, float* __restrict__ out,
                int n_atoms) {
    extern __shared__ char smem[];
    u64*   hsu = (u64*)smem;
    float* hsf = (float*)smem;
    float* Ws  = (float*)(smem + WS_OFF);
    float* Wfs = (float*)(smem + WFS_OFF);
    float* bss = (float*)(smem + BS_OFF);

    const int t = threadIdx.x;
    const int rowbase = blockIdx.x * MLP_ROWS;

    for (int idx = t; idx < MLP_ROWS * EMB; idx += 1024) {
        const int r = idx >> 7, c = idx & 127;
        const int gr = rowbase + r;
        const float v = (gr < n_atoms) ? g_h[(size_t)gr * EMB + c] : 0.f;
        hsf[c * (2 * PH) + r] = v;
    }
    if (t < EMB) {
#pragma unroll
        for (int c = 0; c < NT; ++c) Wfs[t * NTP + c] = Wf[t * NT + c];
    }

    const int j0 = (t & 63) * 2;
    const int pg = t >> 6;

    for (int li = 0; li < NDENSE; ++li) {
        const float* W = dW + (size_t)li * EMB * EMB;
        for (int idx = t; idx < EMB * EMB; idx += 1024) Ws[idx] = W[idx];
        if (t < EMB) bss[t] = dB[li * EMB + t];
        __syncthreads();

        u64 acc[5][2];
#pragma unroll
        for (int p = 0; p < 5; ++p) { acc[p][0] = 0ull; acc[p][1] = 0ull; }

#pragma unroll 4
        for (int k = 0; k < EMB; ++k) {
            const float2 wv = *(const float2*)&Ws[k * EMB + j0];
            const u64 w0 = pack2(wv.x, wv.x);
            const u64 w1 = pack2(wv.y, wv.y);
            const u64* hrow = hsu + k * PH;
#pragma unroll
            for (int p = 0; p < 4; ++p) {
                const u64 hv = hrow[pg + p * 16];
                acc[p][0] = ffma2(hv, w0, acc[p][0]);
                acc[p][1] = ffma2(hv, w1, acc[p][1]);
            }
            if (pg < 4) {
                const u64 hv = hrow[64 + pg];
                acc[4][0] = ffma2(hv, w0, acc[4][0]);
                acc[4][1] = ffma2(hv, w1, acc[4][1]);
            }
        }

        const float b0 = bss[j0], b1 = bss[j0 + 1];
        __syncthreads();

#pragma unroll
        for (int p = 0; p < 5; ++p) {
            if (p == 4 && pg >= 4) break;
            const int pr = (p < 4) ? (pg + p * 16) : (64 + pg);
            float lo, hi;
            unpack2(acc[p][0], lo, hi);
            lo = silu_f(lo + b0); hi = silu_f(hi + b0);
            hsu[j0 * PH + pr] = pack2(lo, hi);
            unpack2(acc[p][1], lo, hi);
            lo = silu_f(lo + b1); hi = silu_f(hi + b1);
            hsu[(j0 + 1) * PH + pr] = pack2(lo, hi);
        }
        __syncthreads();
    }

    const int c = t & 15;
    const int grp = t >> 4;
    if (c < NT) {
#pragma unroll
        for (int i = 0; i < 2; ++i) {
            const int pr = grp + 64 * i;
            if (pr < MLP_PAIRS) {
                u64 acc = 0ull;
#pragma unroll 4
                for (int k = 0; k < EMB; ++k) {
                    const float wfv = Wfs[k * NTP + c];
                    acc = ffma2(hsu[k * PH + pr], pack2(wfv, wfv), acc);
                }
                float lo, hi;
                unpack2(acc, lo, hi);
                const int r0 = rowbase + 2 * pr;
                if (r0 < n_atoms)     out[(size_t)r0 * NT + c]       = lo;
                if (r0 + 1 < n_atoms) out[(size_t)(r0 + 1) * NT + c] = hi;
            }
        }
    }
}

// ===================================================================
extern "C" void kernel_launch(void* const* d_in, const int* in_sizes, int n_in,
                              void* d_out, int out_size) {
    const float* x    = (const float*)d_in[0];
    const float* rbf  = (const float*)d_in[1];
    const void*  idnb =               d_in[2];
    const float* Wrbf = (const float*)d_in[4];
    const float* dW   = (const float*)d_in[5];
    const float* dB   = (const float*)d_in[6];
    const float* Wf   = (const float*)d_in[7];
    float* out = (float*)d_out;

    const int E = in_sizes[0] / EMB;
    const int n_atoms = out_size / NT;

    hist_kernel<<<592, 256>>>(idnb, E, n_atoms);            // 0
    scan_kernel<<<1, 1024>>>(n_atoms, E);                   // 1
    fill_kernel<<<592, 256>>>(idnb, E, n_atoms);            // 2
    gather_kernel<<<592, 256>>>(x, rbf, Wrbf, n_atoms);     // 3 (profiled)

    cudaFuncSetAttribute(mlp_kernel, cudaFuncAttributeMaxDynamicSharedMemorySize,
                         SMEM_TOTAL);
    const int blocks = (n_atoms + MLP_ROWS - 1) / MLP_ROWS;
    mlp_kernel<<<blocks, 1024, SMEM_TOTAL>>>(dW, dB, Wf, out, n_atoms);  // 4
}